// round 9
// baseline (speedup 1.0000x reference)
#include <cuda_runtime.h>
#include <cstdint>

#define NPTS 8192
#define KNN  8

typedef unsigned long long u64t;

// packed fp32x2 helpers (FFMA2 path — only reachable via PTX on sm_103a)
__device__ __forceinline__ u64t pk2(float x) {
    u64t r; asm("mov.b64 %0, {%1, %1};" : "=l"(r) : "f"(x)); return r;
}
__device__ __forceinline__ u64t f2fma(u64t a, u64t b, u64t c) {
    u64t d; asm("fma.rn.f32x2 %0, %1, %2, %3;" : "=l"(d) : "l"(a), "l"(b), "l"(c)); return d;
}
__device__ __forceinline__ float2 up2(u64t v) {
    float2 f; asm("mov.b64 {%0, %1}, %2;" : "=f"(f.x), "=f"(f.y) : "l"(v)); return f;
}

// ---------------- scratch (static device globals; no allocation) ----------------
__device__ __align__(16) float4 g_pts4[NPTS];              // x,y,z,|x|^2
__device__ int                  g_idx[NPTS * KNN];         // knn indices (flat)
__device__ __align__(16) float  g_qp1[NPTS * 128];         // [i][0:64]=qA1, [64:128]=pB1
__device__ __align__(16) float  g_x1 [NPTS * 128];         // EdgeConv1 output
__device__ __align__(16) float  g_qp2[NPTS * 256];         // [i][0:128]=qA2, [128:256]=pB2
__device__ __align__(16) float  g_wcat[128 * 256];         // [W3a-W3b | W3b]

// ---------------- prep: pack points + squared norms ----------------
__global__ void k_prep(const float* __restrict__ pc) {
    int i = blockIdx.x * blockDim.x + threadIdx.x;
    if (i < NPTS) {
        float x = pc[3*i], y = pc[3*i+1], z = pc[3*i+2];
        float s = fmaf(x, x, fmaf(y, y, z*z));
        g_pts4[i] = make_float4(x, y, z, s);
    }
}

// ---------------- KNN: block = 64 points x 4 parts, all pts in smem ----------------
__global__ void k_knn() {
    extern __shared__ char sm[];
    float4* sp = (float4*)sm;                                   // 8192 float4 = 128KB
    float*  md = (float*)(sm + NPTS * 16);                      // 64*33 floats
    int*    mi = (int*)  (sm + NPTS * 16 + 64 * 33 * 4);        // 64*33 ints

    int tid = threadIdx.x;
    for (int t = tid; t < NPTS; t += 256) sp[t] = g_pts4[t];
    __syncthreads();

    int part = tid >> 6;             // warp-uniform
    int lp   = tid & 63;
    int pt   = blockIdx.x * 64 + lp;
    float4 me = sp[pt];

    float bd[8]; int bj[8];
#pragma unroll
    for (int s = 0; s < 8; s++) { bd[s] = 3.4e38f; bj[s] = 0x7fffffff; }

    int j0 = part * 2048;
#pragma unroll 4
    for (int jj = 0; jj < 2048; jj++) {
        int j = j0 + jj;
        float4 o = sp[j];
        float dot = fmaf(me.x, o.x, fmaf(me.y, o.y, me.z * o.z));
        float d   = fmaf(-2.0f, dot, me.w + o.w);
        if (d < bd[7]) {                            // strict <: earlier (lower) j wins ties
            bd[7] = d; bj[7] = j;
#pragma unroll
            for (int s = 7; s > 0; s--) {
                if (bd[s] < bd[s-1]) {
                    float td = bd[s]; bd[s] = bd[s-1]; bd[s-1] = td;
                    int   tj = bj[s]; bj[s] = bj[s-1]; bj[s-1] = tj;
                }
            }
        }
    }
#pragma unroll
    for (int s = 0; s < 8; s++) {
        md[lp * 33 + part * 8 + s] = bd[s];
        mi[lp * 33 + part * 8 + s] = bj[s];
    }
    __syncthreads();

    if (tid < 64) {                 // 4-way merge: 8 passes of lex-min over 32
        float* rd = md + tid * 33;
        int*   ri = mi + tid * 33;
        int po = (blockIdx.x * 64 + tid) * KNN;
        for (int s = 0; s < 8; s++) {
            float bdd = 3.4e38f; int bjj = 0x7fffffff; int bp = 0;
            for (int t = 0; t < 32; t++) {
                float dd = rd[t]; int jj = ri[t];
                if (dd < bdd || (dd == bdd && jj < bjj)) { bdd = dd; bjj = jj; bp = t; }
            }
            rd[bp] = 3.4e38f;
            g_idx[po + s] = bjj;
        }
    }
}

// ---------------- P1: x(8192,3) -> qA1 (x@(W1a-W1b)) | pB1 (x@W1b), 64 cols each ----------------
__global__ void k_lin1(const float* __restrict__ W1, const float* __restrict__ pc) {
    int g = blockIdx.x * blockDim.x + threadIdx.x;      // NPTS*32 tasks (float4 each)
    if (g >= NPTS * 32) return;
    int i = g >> 5, q = g & 31;
    float x0 = pc[3*i], x1 = pc[3*i+1], x2 = pc[3*i+2];
    bool isQ = (q < 16);
    int c = (isQ ? q : q - 16) * 4;
    float v[4];
#pragma unroll
    for (int u = 0; u < 4; u++) {
        float wa0 = W1[0*64 + c+u], wa1 = W1[1*64 + c+u], wa2 = W1[2*64 + c+u];
        float wb0 = W1[3*64 + c+u], wb1 = W1[4*64 + c+u], wb2 = W1[5*64 + c+u];
        if (isQ) v[u] = x0*(wa0-wb0) + x1*(wa1-wb1) + x2*(wa2-wb2);
        else     v[u] = x0*wb0 + x1*wb1 + x2*wb2;
    }
    *(float4*)&g_qp1[i * 128 + q * 4] = make_float4(v[0], v[1], v[2], v[3]);
}

// ---------------- build Wcat = [W3a - W3b | W3b]  (128 x 256) ----------------
__global__ void k_wcat(const float* __restrict__ W3) {
    int g = blockIdx.x * blockDim.x + threadIdx.x;      // 128*256
    if (g >= 128 * 256) return;
    int m = g >> 8, n = g & 255;
    float v;
    if (n < 128) v = W3[m * 128 + n] - W3[(m + 128) * 128 + n];
    else         v = W3[(m + 128) * 128 + (n - 128)];
    g_wcat[m * 256 + n] = v;
}

// ---------------- fused GEMM: 128x128 block tile, 8x16 per-thread microtile ----------------
// 128 threads. Thread: rowg = tid>>3 (rows rowg*8..+8), colg = tid&7 (cols colg*16..+16).
// Per thread-c: 64 FFMA2, 6 LDS.128, 8 pk2 -> fma-pipe bound (L1 demand ~30% of fma).
// K processed in KC=64 chunks (A smem 32KB); W N-tile (128 cols) resident (KDIM*512B).
// EDGE: thread's 8 rows = one point's 8 edges -> max fully register-local, no shfl.
template<int KDIM, int NOUT, bool EDGE, bool RELU_OUT>
__global__ void __launch_bounds__(128, 2) k_gemm(
    const float* __restrict__ qA, const float* __restrict__ pB, int qstride,
    const float* __restrict__ bK, const float* __restrict__ Wg,
    const float* __restrict__ bN, float* __restrict__ out)
{
    const int KC = 64;
    extern __shared__ float smf[];
    float* As = smf;                  // [KC][128]
    float* Ws = smf + KC * 128;       // [KDIM][128]  (this block's N-tile)
    int tid = threadIdx.x;
    int blk = blockIdx.x;
    int nt0 = blockIdx.y * 128;

    // load weight N-tile (row-major slice of Wg[KDIM][NOUT])
    {
        float4*       Ws4 = (float4*)Ws;
        const float4* Wg4 = (const float4*)Wg;
#pragma unroll 4
        for (int t = tid; t < KDIM * 32; t += 128) {
            int c = t >> 5, col4 = t & 31;
            Ws4[c * 32 + col4] = Wg4[(c * NOUT + nt0) / 4 + col4];
        }
    }

    int rowg = tid >> 3;      // 0..15 -> rows rowg*8..+8
    int colg = tid & 7;       // 0..7  -> cols colg*16..+16

    u64t acc2[8][8];          // [row r][colpair np]: cols (colg*16+2np, +2np+1)
#pragma unroll
    for (int r = 0; r < 8; r++)
#pragma unroll
        for (int n = 0; n < 8; n++) acc2[r][n] = 0ull;

    int base = blk * 128;

    for (int kc = 0; kc < KDIM / KC; kc++) {
        __syncthreads();          // protect As reuse across chunks (and after W load)
        // generate A chunk (transposed: As[c][rr]), cols kc*KC .. kc*KC+KC
        for (int t = tid; t < 128 * (KC / 4); t += 128) {
            int rr = t & 127, c4 = t >> 7;
            int coff = kc * KC + c4 * 4;
            float4 v;
            if (EDGE) {
                int i = (base + rr) >> 3;
                int j = g_idx[base + rr];
                float4 q = *(const float4*)&qA[i * qstride + coff];
                float4 p = *(const float4*)&pB[(long)j * qstride + coff];
                float4 b = *(const float4*)&bK[coff];
                v.x = fmaxf(q.x + p.x + b.x, 0.0f);
                v.y = fmaxf(q.y + p.y + b.y, 0.0f);
                v.z = fmaxf(q.z + p.z + b.z, 0.0f);
                v.w = fmaxf(q.w + p.w + b.w, 0.0f);
            } else {
                v = *(const float4*)&qA[(long)(base + rr) * qstride + coff];
            }
            As[(c4*4 + 0) * 128 + rr] = v.x;
            As[(c4*4 + 1) * 128 + rr] = v.y;
            As[(c4*4 + 2) * 128 + rr] = v.z;
            As[(c4*4 + 3) * 128 + rr] = v.w;
        }
        __syncthreads();

        const float* Wk = Ws + kc * KC * 128;
#pragma unroll 2
        for (int c = 0; c < KC; c++) {
            const float* ar = &As[c * 128 + rowg * 8];
            float4 a0 = *(const float4*)ar;
            float4 a1 = *(const float4*)(ar + 4);
            u64t ad[8] = {pk2(a0.x), pk2(a0.y), pk2(a0.z), pk2(a0.w),
                          pk2(a1.x), pk2(a1.y), pk2(a1.z), pk2(a1.w)};
            const ulonglong2* wp = (const ulonglong2*)&Wk[c * 128 + colg * 16];
            ulonglong2 w0 = wp[0], w1 = wp[1], w2 = wp[2], w3 = wp[3];
            u64t wv[8] = {w0.x, w0.y, w1.x, w1.y, w2.x, w2.y, w3.x, w3.y};
#pragma unroll
            for (int r = 0; r < 8; r++)
#pragma unroll
                for (int n = 0; n < 8; n++)
                    acc2[r][n] = f2fma(ad[r], wv[n], acc2[r][n]);
        }
    }

    if (EDGE) {
        // thread's 8 rows are exactly point pt's 8 edges -> pure register max
        int pt = blk * 16 + rowg;
        int col0 = nt0 + colg * 16;
        float res[16];
#pragma unroll
        for (int n = 0; n < 8; n++) {
            float2 m = up2(acc2[0][n]);
#pragma unroll
            for (int r = 1; r < 8; r++) {
                float2 v = up2(acc2[r][n]);
                m.x = fmaxf(m.x, v.x);
                m.y = fmaxf(m.y, v.y);
            }
            m.x += bN[col0 + 2*n];
            m.y += bN[col0 + 2*n + 1];
            if (RELU_OUT) { m.x = fmaxf(m.x, 0.0f); m.y = fmaxf(m.y, 0.0f); }
            res[2*n] = m.x; res[2*n+1] = m.y;
        }
#pragma unroll
        for (int q = 0; q < 4; q++)
            *(float4*)&out[(long)pt * NOUT + col0 + 4*q] =
                make_float4(res[4*q], res[4*q+1], res[4*q+2], res[4*q+3]);
    } else {
        int col0 = nt0 + colg * 16;
#pragma unroll
        for (int r = 0; r < 8; r++) {
            long row = base + rowg * 8 + r;
#pragma unroll
            for (int q = 0; q < 4; q++) {
                float2 lo = up2(acc2[r][2*q]);
                float2 hi = up2(acc2[r][2*q + 1]);
                *(float4*)&out[row * NOUT + col0 + 4*q] =
                    make_float4(lo.x, lo.y, hi.x, hi.y);
            }
        }
    }
}

// ---------------- launch ----------------
extern "C" void kernel_launch(void* const* d_in, const int* in_sizes, int n_in,
                              void* d_out, int out_size) {
    const float* pc = (const float*)d_in[0];
    const float* W1 = (const float*)d_in[1];
    const float* b1 = (const float*)d_in[2];
    const float* W2 = (const float*)d_in[3];
    const float* b2 = (const float*)d_in[4];
    const float* W3 = (const float*)d_in[5];
    const float* b3 = (const float*)d_in[6];
    const float* W4 = (const float*)d_in[7];
    const float* b4 = (const float*)d_in[8];
    float* out = (float*)d_out;

    // resolve REAL device addresses of the __device__ scratch symbols
    float *qp1 = nullptr, *x1 = nullptr, *qp2 = nullptr, *wcat = nullptr;
    cudaGetSymbolAddress((void**)&qp1,  g_qp1);
    cudaGetSymbolAddress((void**)&x1,   g_x1);
    cudaGetSymbolAddress((void**)&qp2,  g_qp2);
    cudaGetSymbolAddress((void**)&wcat, g_wcat);

    const int SM_KNN = NPTS * 16 + 2 * 64 * 33 * 4;                 // 147968
    const int SM_EC1 = (64 * 128 + 64 * 128) * 4;                   // 64KB
    const int SM_BIG = (64 * 128 + 128 * 128) * 4;                  // 96KB

    cudaFuncSetAttribute(k_knn, cudaFuncAttributeMaxDynamicSharedMemorySize, SM_KNN);
    cudaFuncSetAttribute((const void*)k_gemm<64,128,true,true>,
                         cudaFuncAttributeMaxDynamicSharedMemorySize, SM_EC1);
    cudaFuncSetAttribute((const void*)k_gemm<128,256,false,false>,
                         cudaFuncAttributeMaxDynamicSharedMemorySize, SM_BIG);
    cudaFuncSetAttribute((const void*)k_gemm<128,256,true,false>,
                         cudaFuncAttributeMaxDynamicSharedMemorySize, SM_BIG);

    // 1. pack points
    k_prep<<<(NPTS + 255) / 256, 256>>>(pc);
    // 2. knn
    k_knn<<<NPTS / 64, 256, SM_KNN>>>();
    // 3. per-point linear factors for EdgeConv1
    k_lin1<<<(NPTS * 32 + 255) / 256, 256>>>(W1, pc);
    // 4. EdgeConv1: edge GEMM (K=64 -> N=128) + max + relu  -> x1
    k_gemm<64,128,true,true><<<dim3(NPTS * KNN / 128, 1), 128, SM_EC1>>>(
        qp1, qp1 + 64, 128, b1, W2, b2, x1);
    // 5. Wcat = [W3a - W3b | W3b]
    k_wcat<<<(128 * 256 + 255) / 256, 256>>>(W3);
    // 6. P2: x1 @ Wcat -> qA2|pB2  (grid.y = 2 N-tiles)
    k_gemm<128,256,false,false><<<dim3(NPTS / 128, 2), 128, SM_BIG>>>(
        x1, nullptr, 128, nullptr, wcat, nullptr, qp2);
    // 7. EdgeConv2: edge GEMM (K=128 -> N=256) + max  -> out  (grid.y = 2 N-tiles)
    k_gemm<128,256,true,false><<<dim3(NPTS * KNN / 128, 2), 128, SM_BIG>>>(
        qp2, qp2 + 128, 256, b3, W4, b4, out);
}

// round 10
// speedup vs baseline: 1.1917x; 1.1917x over previous
#include <cuda_runtime.h>
#include <cstdint>

#define NPTS 8192
#define KNN  8

typedef unsigned long long u64t;

// packed fp32x2 helpers (FFMA2 path — only reachable via PTX on sm_103a)
__device__ __forceinline__ u64t pk2(float x) {
    u64t r; asm("mov.b64 %0, {%1, %1};" : "=l"(r) : "f"(x)); return r;
}
__device__ __forceinline__ u64t f2fma(u64t a, u64t b, u64t c) {
    u64t d; asm("fma.rn.f32x2 %0, %1, %2, %3;" : "=l"(d) : "l"(a), "l"(b), "l"(c)); return d;
}
__device__ __forceinline__ float2 up2(u64t v) {
    float2 f; asm("mov.b64 {%0, %1}, %2;" : "=f"(f.x), "=f"(f.y) : "l"(v)); return f;
}

// ---------------- scratch (static device globals; no allocation) ----------------
__device__ __align__(16) float4 g_pts4[NPTS];              // x,y,z,|x|^2
__device__ int                  g_idx[NPTS * KNN];         // knn indices (flat)
__device__ __align__(16) float  g_qp1[NPTS * 128];         // [i][0:64]=qA1, [64:128]=pB1
__device__ __align__(16) float  g_x1 [NPTS * 128];         // EdgeConv1 output
__device__ __align__(16) float  g_qp2[NPTS * 256];         // [i][0:128]=qA2, [128:256]=pB2
__device__ __align__(16) float  g_wcat[128 * 256];         // [W3a-W3b | W3b]

// ---------------- prep: pack points + squared norms ----------------
__global__ void k_prep(const float* __restrict__ pc) {
    int i = blockIdx.x * blockDim.x + threadIdx.x;
    if (i < NPTS) {
        float x = pc[3*i], y = pc[3*i+1], z = pc[3*i+2];
        float s = fmaf(x, x, fmaf(y, y, z*z));
        g_pts4[i] = make_float4(x, y, z, s);
    }
}

// ---------------- KNN: block = 32 points x 8 parts (grid 256 >= 148 SMs) ----------------
__global__ void k_knn() {
    extern __shared__ char sm[];
    float4* sp = (float4*)sm;                                   // 8192 float4 = 128KB
    float*  md = (float*)(sm + NPTS * 16);                      // 32*65 floats
    int*    mi = (int*)  (sm + NPTS * 16 + 32 * 65 * 4);        // 32*65 ints

    int tid = threadIdx.x;
    for (int t = tid; t < NPTS; t += 256) sp[t] = g_pts4[t];
    __syncthreads();

    int part = tid >> 5;             // 0..7 (warp-uniform)
    int lp   = tid & 31;
    int pt   = blockIdx.x * 32 + lp;
    float4 me = sp[pt];

    float bd[8]; int bj[8];
#pragma unroll
    for (int s = 0; s < 8; s++) { bd[s] = 3.4e38f; bj[s] = 0x7fffffff; }

    int j0 = part * 1024;
#pragma unroll 4
    for (int jj = 0; jj < 1024; jj++) {
        int j = j0 + jj;
        float4 o = sp[j];
        float dot = fmaf(me.x, o.x, fmaf(me.y, o.y, me.z * o.z));
        float d   = fmaf(-2.0f, dot, me.w + o.w);
        if (d < bd[7]) {                            // strict <: earlier (lower) j wins ties
            bd[7] = d; bj[7] = j;
#pragma unroll
            for (int s = 7; s > 0; s--) {
                if (bd[s] < bd[s-1]) {
                    float td = bd[s]; bd[s] = bd[s-1]; bd[s-1] = td;
                    int   tj = bj[s]; bj[s] = bj[s-1]; bj[s-1] = tj;
                }
            }
        }
    }
#pragma unroll
    for (int s = 0; s < 8; s++) {
        md[lp * 65 + part * 8 + s] = bd[s];
        mi[lp * 65 + part * 8 + s] = bj[s];
    }
    __syncthreads();

    if (tid < 32) {                 // 8-way merge: 8 passes of lex-min over 64
        float* rd = md + tid * 65;
        int*   ri = mi + tid * 65;
        int po = (blockIdx.x * 32 + tid) * KNN;
        for (int s = 0; s < 8; s++) {
            float bdd = 3.4e38f; int bjj = 0x7fffffff; int bp = 0;
            for (int t = 0; t < 64; t++) {
                float dd = rd[t]; int jj = ri[t];
                if (dd < bdd || (dd == bdd && jj < bjj)) { bdd = dd; bjj = jj; bp = t; }
            }
            rd[bp] = 3.4e38f;
            g_idx[po + s] = bjj;
        }
    }
}

// ---------------- P1: x(8192,3) -> qA1 (x@(W1a-W1b)) | pB1 (x@W1b), 64 cols each ----------------
__global__ void k_lin1(const float* __restrict__ W1, const float* __restrict__ pc) {
    int g = blockIdx.x * blockDim.x + threadIdx.x;      // NPTS*32 tasks (float4 each)
    if (g >= NPTS * 32) return;
    int i = g >> 5, q = g & 31;
    float x0 = pc[3*i], x1 = pc[3*i+1], x2 = pc[3*i+2];
    bool isQ = (q < 16);
    int c = (isQ ? q : q - 16) * 4;
    float v[4];
#pragma unroll
    for (int u = 0; u < 4; u++) {
        float wa0 = W1[0*64 + c+u], wa1 = W1[1*64 + c+u], wa2 = W1[2*64 + c+u];
        float wb0 = W1[3*64 + c+u], wb1 = W1[4*64 + c+u], wb2 = W1[5*64 + c+u];
        if (isQ) v[u] = x0*(wa0-wb0) + x1*(wa1-wb1) + x2*(wa2-wb2);
        else     v[u] = x0*wb0 + x1*wb1 + x2*wb2;
    }
    *(float4*)&g_qp1[i * 128 + q * 4] = make_float4(v[0], v[1], v[2], v[3]);
}

// ---------------- build Wcat = [W3a - W3b | W3b]  (128 x 256) ----------------
__global__ void k_wcat(const float* __restrict__ W3) {
    int g = blockIdx.x * blockDim.x + threadIdx.x;      // 128*256
    if (g >= 128 * 256) return;
    int m = g >> 8, n = g & 255;
    float v;
    if (n < 128) v = W3[m * 128 + n] - W3[(m + 128) * 128 + n];
    else         v = W3[(m + 128) * 128 + (n - 128)];
    g_wcat[m * 256 + n] = v;
}

// ---------------- fused GEMM (R5 mainloop shape) + W K-chunking for occupancy ----------------
// Block: 64 rows x 128 cols (N-tile), 256 threads. A tile full-K in smem; W tile
// loaded in KC-row chunks (32KB) so BIG smem = 64KB -> 3 blocks/SM (was 96KB/2).
// Thread microtile: 8 k-rows (packed pairs, straight from smem) x 4 cols; 4 pk2/c (w dup).
template<int KDIM, int KC, int NOUT, bool EDGE, bool RELU_OUT>
__global__ void __launch_bounds__(256) k_gemm(
    const float* __restrict__ qA, const float* __restrict__ pB, int qstride,
    const float* __restrict__ bK, const float* __restrict__ Wg,
    const float* __restrict__ bN, float* __restrict__ out)
{
    extern __shared__ float smf[];
    float* As = smf;                  // [KDIM][64]
    float* Ws = smf + KDIM * 64;      // [KC][128]  (current W chunk of this N-tile)
    int tid = threadIdx.x;
    int blk = blockIdx.x;
    int nt0 = blockIdx.y * 128;

    // generate A tile (transposed: As[c][rr]) — full K, once
    {
        const int TASKS = 64 * (KDIM / 4);
        int base64 = blk * 64;
        for (int t = tid; t < TASKS; t += 256) {
            int rr = t & 63, c4 = t >> 6;
            float4 v;
            if (EDGE) {
                int i = (base64 + rr) >> 3;
                int j = g_idx[base64 + rr];
                float4 q = *(const float4*)&qA[i * qstride + c4 * 4];
                float4 p = *(const float4*)&pB[(long)j * qstride + c4 * 4];
                float4 b = *(const float4*)&bK[c4 * 4];
                v.x = fmaxf(q.x + p.x + b.x, 0.0f);
                v.y = fmaxf(q.y + p.y + b.y, 0.0f);
                v.z = fmaxf(q.z + p.z + b.z, 0.0f);
                v.w = fmaxf(q.w + p.w + b.w, 0.0f);
            } else {
                v = *(const float4*)&qA[(long)(base64 + rr) * qstride + c4 * 4];
            }
            As[(c4*4 + 0) * 64 + rr] = v.x;
            As[(c4*4 + 1) * 64 + rr] = v.y;
            As[(c4*4 + 2) * 64 + rr] = v.z;
            As[(c4*4 + 3) * 64 + rr] = v.w;
        }
    }

    int tm = tid >> 5;        // warp id -> all lanes share tm => A smem loads broadcast
    int tn = tid & 31;        // lane -> consecutive 16B W loads (conflict-free)

    u64t acc2[4][4];          // [k-pair p][col n]: packed {kk=2p,kk=2p+1} for col tn*4+n
#pragma unroll
    for (int p = 0; p < 4; p++)
#pragma unroll
        for (int n = 0; n < 4; n++) acc2[p][n] = 0ull;

    const float4* Wg4 = (const float4*)Wg;
    for (int kc = 0; kc < KDIM / KC; kc++) {
        __syncthreads();      // A ready (first iter) / previous chunk consumed
        // load W chunk [kc*KC .. kc*KC+KC) x this N-tile
        {
            float4* Ws4 = (float4*)Ws;
#pragma unroll 4
            for (int t = tid; t < KC * 32; t += 256) {
                int c = t >> 5, col4 = t & 31;
                Ws4[c * 32 + col4] = Wg4[((kc * KC + c) * NOUT + nt0) / 4 + col4];
            }
        }
        __syncthreads();

        const float* Ak = As + kc * KC * 64;
#pragma unroll 4
        for (int c = 0; c < KC; c++) {
            // a-pairs: adjacent rr floats load directly as packed f32x2 (no pack instr)
            ulonglong2 av0 = *(const ulonglong2*)&Ak[c * 64 + tm * 8];      // {a0,a1},{a2,a3}
            ulonglong2 av1 = *(const ulonglong2*)&Ak[c * 64 + tm * 8 + 4];  // {a4,a5},{a6,a7}
            u64t ap[4] = {av0.x, av0.y, av1.x, av1.y};
            float4 w = *(const float4*)&Ws[c * 128 + tn * 4];
            u64t wd[4] = {pk2(w.x), pk2(w.y), pk2(w.z), pk2(w.w)};          // 4 packs/iter
#pragma unroll
            for (int p = 0; p < 4; p++) {
#pragma unroll
                for (int n = 0; n < 4; n++)
                    acc2[p][n] = f2fma(ap[p], wd[n], acc2[p][n]);
            }
        }
    }

    if (EDGE) {
        int pt = blk * 8 + tm;        // one point per warp-row => max is register-local
        float res[4];
#pragma unroll
        for (int n = 0; n < 4; n++) {
            float2 v0 = up2(acc2[0][n]);
            float2 v1 = up2(acc2[1][n]);
            float2 v2 = up2(acc2[2][n]);
            float2 v3 = up2(acc2[3][n]);
            float m = fmaxf(fmaxf(fmaxf(v0.x, v0.y), fmaxf(v1.x, v1.y)),
                            fmaxf(fmaxf(v2.x, v2.y), fmaxf(v3.x, v3.y)));
            m += bN[nt0 + tn * 4 + n];
            if (RELU_OUT) m = fmaxf(m, 0.0f);
            res[n] = m;
        }
        *(float4*)&out[(long)pt * NOUT + nt0 + tn * 4] =
            make_float4(res[0], res[1], res[2], res[3]);
    } else {
        int base = blk * 64;
#pragma unroll
        for (int p = 0; p < 4; p++) {
            float2 c0 = up2(acc2[p][0]);
            float2 c1 = up2(acc2[p][1]);
            float2 c2 = up2(acc2[p][2]);
            float2 c3 = up2(acc2[p][3]);
            int row0 = base + tm * 8 + 2 * p;
            *(float4*)&out[(long)row0 * NOUT + nt0 + tn * 4] =
                make_float4(c0.x, c1.x, c2.x, c3.x);
            *(float4*)&out[(long)(row0 + 1) * NOUT + nt0 + tn * 4] =
                make_float4(c0.y, c1.y, c2.y, c3.y);
        }
    }
}

// ---------------- launch ----------------
extern "C" void kernel_launch(void* const* d_in, const int* in_sizes, int n_in,
                              void* d_out, int out_size) {
    const float* pc = (const float*)d_in[0];
    const float* W1 = (const float*)d_in[1];
    const float* b1 = (const float*)d_in[2];
    const float* W2 = (const float*)d_in[3];
    const float* b2 = (const float*)d_in[4];
    const float* W3 = (const float*)d_in[5];
    const float* b3 = (const float*)d_in[6];
    const float* W4 = (const float*)d_in[7];
    const float* b4 = (const float*)d_in[8];
    float* out = (float*)d_out;

    // resolve REAL device addresses of the __device__ scratch symbols
    float *qp1 = nullptr, *x1 = nullptr, *qp2 = nullptr, *wcat = nullptr;
    cudaGetSymbolAddress((void**)&qp1,  g_qp1);
    cudaGetSymbolAddress((void**)&x1,   g_x1);
    cudaGetSymbolAddress((void**)&qp2,  g_qp2);
    cudaGetSymbolAddress((void**)&wcat, g_wcat);

    const int SM_KNN = NPTS * 16 + 32 * 65 * 8;                     // 147.7KB
    const int SM_EC1 = (64 * 64 + 64 * 128) * 4;                    // 48KB -> 4 blocks/SM
    const int SM_BIG = (128 * 64 + 64 * 128) * 4;                   // 64KB -> 3 blocks/SM

    cudaFuncSetAttribute(k_knn, cudaFuncAttributeMaxDynamicSharedMemorySize, SM_KNN);
    cudaFuncSetAttribute((const void*)k_gemm<64,64,128,true,true>,
                         cudaFuncAttributeMaxDynamicSharedMemorySize, SM_EC1);
    cudaFuncSetAttribute((const void*)k_gemm<128,64,256,false,false>,
                         cudaFuncAttributeMaxDynamicSharedMemorySize, SM_BIG);
    cudaFuncSetAttribute((const void*)k_gemm<128,64,256,true,false>,
                         cudaFuncAttributeMaxDynamicSharedMemorySize, SM_BIG);

    // 1. pack points
    k_prep<<<(NPTS + 255) / 256, 256>>>(pc);
    // 2. knn (256 blocks -> full chip)
    k_knn<<<NPTS / 32, 256, SM_KNN>>>();
    // 3. per-point linear factors for EdgeConv1
    k_lin1<<<(NPTS * 32 + 255) / 256, 256>>>(W1, pc);
    // 4. EdgeConv1: edge GEMM (K=64 -> N=128) + max + relu  -> x1
    k_gemm<64,64,128,true,true><<<dim3(NPTS * KNN / 64, 1), 256, SM_EC1>>>(
        qp1, qp1 + 64, 128, b1, W2, b2, x1);
    // 5. Wcat = [W3a - W3b | W3b]
    k_wcat<<<(128 * 256 + 255) / 256, 256>>>(W3);
    // 6. P2: x1 @ Wcat -> qA2|pB2  (grid.y = 2 N-tiles)
    k_gemm<128,64,256,false,false><<<dim3(NPTS / 64, 2), 256, SM_BIG>>>(
        x1, nullptr, 128, nullptr, wcat, nullptr, qp2);
    // 7. EdgeConv2: edge GEMM (K=128 -> N=256) + max  -> out  (grid.y = 2 N-tiles)
    k_gemm<128,64,256,true,false><<<dim3(NPTS * KNN / 64, 2), 256, SM_BIG>>>(
        qp2, qp2 + 128, 256, b3, W4, b4, out);
}

// round 11
// speedup vs baseline: 1.3268x; 1.1134x over previous
#include <cuda_runtime.h>
#include <cstdint>

#define NPTS 8192
#define KNN  8

typedef unsigned long long u64t;

// packed fp32x2 helpers (FFMA2 path — only reachable via PTX on sm_103a)
__device__ __forceinline__ u64t pk2(float x) {
    u64t r; asm("mov.b64 %0, {%1, %1};" : "=l"(r) : "f"(x)); return r;
}
__device__ __forceinline__ u64t f2fma(u64t a, u64t b, u64t c) {
    u64t d; asm("fma.rn.f32x2 %0, %1, %2, %3;" : "=l"(d) : "l"(a), "l"(b), "l"(c)); return d;
}
__device__ __forceinline__ float2 up2(u64t v) {
    float2 f; asm("mov.b64 {%0, %1}, %2;" : "=f"(f.x), "=f"(f.y) : "l"(v)); return f;
}

// ---------------- scratch (static device globals; no allocation) ----------------
__device__ __align__(16) float4 g_pts4[NPTS];              // x,y,z,|x|^2
__device__ int                  g_idx[NPTS * KNN];         // knn indices (flat)
__device__ __align__(16) float  g_qp1[NPTS * 128];         // [i][0:64]=qA1, [64:128]=pB1
__device__ __align__(16) float  g_x1 [NPTS * 128];         // EdgeConv1 output
__device__ __align__(16) float  g_qp2[NPTS * 256];         // [i][0:128]=qA2, [128:256]=pB2
__device__ __align__(16) float  g_wcat[128 * 256];         // [W3a-W3b | W3b]

// ---------------- prep: pack points + squared norms ----------------
__global__ void k_prep(const float* __restrict__ pc) {
    int i = blockIdx.x * blockDim.x + threadIdx.x;
    if (i < NPTS) {
        float x = pc[3*i], y = pc[3*i+1], z = pc[3*i+2];
        float s = fmaf(x, x, fmaf(y, y, z*z));
        g_pts4[i] = make_float4(x, y, z, s);
    }
}

// ---------------- KNN (R5 shape): block = 64 points x 4 parts, all pts in smem ----------------
__global__ void k_knn() {
    extern __shared__ char sm[];
    float4* sp = (float4*)sm;                                   // 8192 float4 = 128KB
    float*  md = (float*)(sm + NPTS * 16);                      // 64*33 floats
    int*    mi = (int*)  (sm + NPTS * 16 + 64 * 33 * 4);        // 64*33 ints

    int tid = threadIdx.x;
    for (int t = tid; t < NPTS; t += 256) sp[t] = g_pts4[t];
    __syncthreads();

    int part = tid >> 6;             // warp-uniform
    int lp   = tid & 63;
    int pt   = blockIdx.x * 64 + lp;
    float4 me = sp[pt];

    float bd[8]; int bj[8];
#pragma unroll
    for (int s = 0; s < 8; s++) { bd[s] = 3.4e38f; bj[s] = 0x7fffffff; }

    int j0 = part * 2048;
#pragma unroll 4
    for (int jj = 0; jj < 2048; jj++) {
        int j = j0 + jj;
        float4 o = sp[j];
        float dot = fmaf(me.x, o.x, fmaf(me.y, o.y, me.z * o.z));
        float d   = fmaf(-2.0f, dot, me.w + o.w);
        if (d < bd[7]) {                            // strict <: earlier (lower) j wins ties
            bd[7] = d; bj[7] = j;
#pragma unroll
            for (int s = 7; s > 0; s--) {
                if (bd[s] < bd[s-1]) {
                    float td = bd[s]; bd[s] = bd[s-1]; bd[s-1] = td;
                    int   tj = bj[s]; bj[s] = bj[s-1]; bj[s-1] = tj;
                }
            }
        }
    }
#pragma unroll
    for (int s = 0; s < 8; s++) {
        md[lp * 33 + part * 8 + s] = bd[s];
        mi[lp * 33 + part * 8 + s] = bj[s];
    }
    __syncthreads();

    if (tid < 64) {                 // 4-way merge: 8 passes of lex-min over 32
        float* rd = md + tid * 33;
        int*   ri = mi + tid * 33;
        int po = (blockIdx.x * 64 + tid) * KNN;
        for (int s = 0; s < 8; s++) {
            float bdd = 3.4e38f; int bjj = 0x7fffffff; int bp = 0;
            for (int t = 0; t < 32; t++) {
                float dd = rd[t]; int jj = ri[t];
                if (dd < bdd || (dd == bdd && jj < bjj)) { bdd = dd; bjj = jj; bp = t; }
            }
            rd[bp] = 3.4e38f;
            g_idx[po + s] = bjj;
        }
    }
}

// ---------------- P1: x(8192,3) -> qA1 (x@(W1a-W1b)) | pB1 (x@W1b), 64 cols each ----------------
__global__ void k_lin1(const float* __restrict__ W1, const float* __restrict__ pc) {
    int g = blockIdx.x * blockDim.x + threadIdx.x;      // NPTS*32 tasks (float4 each)
    if (g >= NPTS * 32) return;
    int i = g >> 5, q = g & 31;
    float x0 = pc[3*i], x1 = pc[3*i+1], x2 = pc[3*i+2];
    bool isQ = (q < 16);
    int c = (isQ ? q : q - 16) * 4;
    float v[4];
#pragma unroll
    for (int u = 0; u < 4; u++) {
        float wa0 = W1[0*64 + c+u], wa1 = W1[1*64 + c+u], wa2 = W1[2*64 + c+u];
        float wb0 = W1[3*64 + c+u], wb1 = W1[4*64 + c+u], wb2 = W1[5*64 + c+u];
        if (isQ) v[u] = x0*(wa0-wb0) + x1*(wa1-wb1) + x2*(wa2-wb2);
        else     v[u] = x0*wb0 + x1*wb1 + x2*wb2;
    }
    *(float4*)&g_qp1[i * 128 + q * 4] = make_float4(v[0], v[1], v[2], v[3]);
}

// ---------------- build Wcat = [W3a - W3b | W3b]  (128 x 256) ----------------
__global__ void k_wcat(const float* __restrict__ W3) {
    int g = blockIdx.x * blockDim.x + threadIdx.x;      // 128*256
    if (g >= 128 * 256) return;
    int m = g >> 8, n = g & 255;
    float v;
    if (n < 128) v = W3[m * 128 + n] - W3[(m + 128) * 128 + n];
    else         v = W3[(m + 128) * 128 + (n - 128)];
    g_wcat[m * 256 + n] = v;
}

// ---------------- fused GEMM (R10 shape): R5 mainloop + W K-chunking ----------------
// Block: 64 rows x 128 cols (N-tile), 256 threads. A tile full-K in smem; W tile
// loaded in KC-row chunks (32KB) so BIG smem = 64KB -> 3 blocks/SM.
// Thread microtile: 8 k-rows (packed pairs, straight from smem) x 4 cols; 4 pk2/c (w dup).
template<int KDIM, int KC, int NOUT, bool EDGE, bool RELU_OUT>
__global__ void __launch_bounds__(256) k_gemm(
    const float* __restrict__ qA, const float* __restrict__ pB, int qstride,
    const float* __restrict__ bK, const float* __restrict__ Wg,
    const float* __restrict__ bN, float* __restrict__ out)
{
    extern __shared__ float smf[];
    float* As = smf;                  // [KDIM][64]
    float* Ws = smf + KDIM * 64;      // [KC][128]  (current W chunk of this N-tile)
    int tid = threadIdx.x;
    int blk = blockIdx.x;
    int nt0 = blockIdx.y * 128;

    // generate A tile (transposed: As[c][rr]) — full K, once
    {
        const int TASKS = 64 * (KDIM / 4);
        int base64 = blk * 64;
        for (int t = tid; t < TASKS; t += 256) {
            int rr = t & 63, c4 = t >> 6;
            float4 v;
            if (EDGE) {
                int i = (base64 + rr) >> 3;
                int j = g_idx[base64 + rr];
                float4 q = *(const float4*)&qA[i * qstride + c4 * 4];
                float4 p = *(const float4*)&pB[(long)j * qstride + c4 * 4];
                float4 b = *(const float4*)&bK[c4 * 4];
                v.x = fmaxf(q.x + p.x + b.x, 0.0f);
                v.y = fmaxf(q.y + p.y + b.y, 0.0f);
                v.z = fmaxf(q.z + p.z + b.z, 0.0f);
                v.w = fmaxf(q.w + p.w + b.w, 0.0f);
            } else {
                v = *(const float4*)&qA[(long)(base64 + rr) * qstride + c4 * 4];
            }
            As[(c4*4 + 0) * 64 + rr] = v.x;
            As[(c4*4 + 1) * 64 + rr] = v.y;
            As[(c4*4 + 2) * 64 + rr] = v.z;
            As[(c4*4 + 3) * 64 + rr] = v.w;
        }
    }

    int tm = tid >> 5;        // warp id -> all lanes share tm => A smem loads broadcast
    int tn = tid & 31;        // lane -> consecutive 16B W loads (conflict-free)

    u64t acc2[4][4];          // [k-pair p][col n]: packed {kk=2p,kk=2p+1} for col tn*4+n
#pragma unroll
    for (int p = 0; p < 4; p++)
#pragma unroll
        for (int n = 0; n < 4; n++) acc2[p][n] = 0ull;

    const float4* Wg4 = (const float4*)Wg;
    for (int kc = 0; kc < KDIM / KC; kc++) {
        __syncthreads();      // A ready (first iter) / previous chunk consumed
        // load W chunk [kc*KC .. kc*KC+KC) x this N-tile
        {
            float4* Ws4 = (float4*)Ws;
#pragma unroll 4
            for (int t = tid; t < KC * 32; t += 256) {
                int c = t >> 5, col4 = t & 31;
                Ws4[c * 32 + col4] = Wg4[((kc * KC + c) * NOUT + nt0) / 4 + col4];
            }
        }
        __syncthreads();

        const float* Ak = As + kc * KC * 64;
#pragma unroll 4
        for (int c = 0; c < KC; c++) {
            // a-pairs: adjacent rr floats load directly as packed f32x2 (no pack instr)
            ulonglong2 av0 = *(const ulonglong2*)&Ak[c * 64 + tm * 8];      // {a0,a1},{a2,a3}
            ulonglong2 av1 = *(const ulonglong2*)&Ak[c * 64 + tm * 8 + 4];  // {a4,a5},{a6,a7}
            u64t ap[4] = {av0.x, av0.y, av1.x, av1.y};
            float4 w = *(const float4*)&Ws[c * 128 + tn * 4];
            u64t wd[4] = {pk2(w.x), pk2(w.y), pk2(w.z), pk2(w.w)};          // 4 packs/iter
#pragma unroll
            for (int p = 0; p < 4; p++) {
#pragma unroll
                for (int n = 0; n < 4; n++)
                    acc2[p][n] = f2fma(ap[p], wd[n], acc2[p][n]);
            }
        }
    }

    if (EDGE) {
        int pt = blk * 8 + tm;        // one point per warp-row => max is register-local
        float res[4];
#pragma unroll
        for (int n = 0; n < 4; n++) {
            float2 v0 = up2(acc2[0][n]);
            float2 v1 = up2(acc2[1][n]);
            float2 v2 = up2(acc2[2][n]);
            float2 v3 = up2(acc2[3][n]);
            float m = fmaxf(fmaxf(fmaxf(v0.x, v0.y), fmaxf(v1.x, v1.y)),
                            fmaxf(fmaxf(v2.x, v2.y), fmaxf(v3.x, v3.y)));
            m += bN[nt0 + tn * 4 + n];
            if (RELU_OUT) m = fmaxf(m, 0.0f);
            res[n] = m;
        }
        *(float4*)&out[(long)pt * NOUT + nt0 + tn * 4] =
            make_float4(res[0], res[1], res[2], res[3]);
    } else {
        int base = blk * 64;
#pragma unroll
        for (int p = 0; p < 4; p++) {
            float2 c0 = up2(acc2[p][0]);
            float2 c1 = up2(acc2[p][1]);
            float2 c2 = up2(acc2[p][2]);
            float2 c3 = up2(acc2[p][3]);
            int row0 = base + tm * 8 + 2 * p;
            *(float4*)&out[(long)row0 * NOUT + nt0 + tn * 4] =
                make_float4(c0.x, c1.x, c2.x, c3.x);
            *(float4*)&out[(long)(row0 + 1) * NOUT + nt0 + tn * 4] =
                make_float4(c0.y, c1.y, c2.y, c3.y);
        }
    }
}

// ---------------- launch ----------------
extern "C" void kernel_launch(void* const* d_in, const int* in_sizes, int n_in,
                              void* d_out, int out_size) {
    const float* pc = (const float*)d_in[0];
    const float* W1 = (const float*)d_in[1];
    const float* b1 = (const float*)d_in[2];
    const float* W2 = (const float*)d_in[3];
    const float* b2 = (const float*)d_in[4];
    const float* W3 = (const float*)d_in[5];
    const float* b3 = (const float*)d_in[6];
    const float* W4 = (const float*)d_in[7];
    const float* b4 = (const float*)d_in[8];
    float* out = (float*)d_out;

    // resolve REAL device addresses of the __device__ scratch symbols
    float *qp1 = nullptr, *x1 = nullptr, *qp2 = nullptr, *wcat = nullptr;
    cudaGetSymbolAddress((void**)&qp1,  g_qp1);
    cudaGetSymbolAddress((void**)&x1,   g_x1);
    cudaGetSymbolAddress((void**)&qp2,  g_qp2);
    cudaGetSymbolAddress((void**)&wcat, g_wcat);

    const int SM_KNN = NPTS * 16 + 2 * 64 * 33 * 4;                 // 147968
    const int SM_EC1 = (64 * 64 + 64 * 128) * 4;                    // 48KB -> 4 blocks/SM
    const int SM_BIG = (128 * 64 + 64 * 128) * 4;                   // 64KB -> 3 blocks/SM

    cudaFuncSetAttribute(k_knn, cudaFuncAttributeMaxDynamicSharedMemorySize, SM_KNN);
    cudaFuncSetAttribute((const void*)k_gemm<64,64,128,true,true>,
                         cudaFuncAttributeMaxDynamicSharedMemorySize, SM_EC1);
    cudaFuncSetAttribute((const void*)k_gemm<128,64,256,false,false>,
                         cudaFuncAttributeMaxDynamicSharedMemorySize, SM_BIG);
    cudaFuncSetAttribute((const void*)k_gemm<128,64,256,true,false>,
                         cudaFuncAttributeMaxDynamicSharedMemorySize, SM_BIG);

    // 1. pack points
    k_prep<<<(NPTS + 255) / 256, 256>>>(pc);
    // 2. knn (R5 shape: 128 blocks of 64 points)
    k_knn<<<NPTS / 64, 256, SM_KNN>>>();
    // 3. per-point linear factors for EdgeConv1
    k_lin1<<<(NPTS * 32 + 255) / 256, 256>>>(W1, pc);
    // 4. EdgeConv1: edge GEMM (K=64 -> N=128) + max + relu  -> x1
    k_gemm<64,64,128,true,true><<<dim3(NPTS * KNN / 64, 1), 256, SM_EC1>>>(
        qp1, qp1 + 64, 128, b1, W2, b2, x1);
    // 5. Wcat = [W3a - W3b | W3b]
    k_wcat<<<(128 * 256 + 255) / 256, 256>>>(W3);
    // 6. P2: x1 @ Wcat -> qA2|pB2  (grid.y = 2 N-tiles)
    k_gemm<128,64,256,false,false><<<dim3(NPTS / 64, 2), 256, SM_BIG>>>(
        x1, nullptr, 128, nullptr, wcat, nullptr, qp2);
    // 7. EdgeConv2: edge GEMM (K=128 -> N=256) + max  -> out  (grid.y = 2 N-tiles)
    k_gemm<128,64,256,true,false><<<dim3(NPTS * KNN / 64, 2), 256, SM_BIG>>>(
        qp2, qp2 + 128, 256, b3, W4, b4, out);
}